// round 7
// baseline (speedup 1.0000x reference)
#include <cuda_runtime.h>
#include <mma.h>
#include <cstdint>

using namespace nvcuda;

#define H 128
#define NP_MAX 100000
#define NA_MAX 50000
#define EC_MAX 1000000
#define EW_MAX 320000

// ---------------- scratch (static device globals; no allocation) ----------------
__device__ float g_aggC[NP_MAX * H];   // mean(cites); later reused as paper tmp (0.5*n1)
__device__ float g_aggW[NP_MAX * H];   // mean(writes)
__device__ float g_aggA[NA_MAX * H];   // mean(rev)
__device__ float g_xp[NP_MAX * H];
__device__ float g_xa[NA_MAX * H];
__device__ int g_degC[NP_MAX];
__device__ int g_degW[NP_MAX];
__device__ int g_degA[NA_MAX];
__device__ int g_offC[NP_MAX];         // after permute: END offsets
__device__ int g_offW[NP_MAX];
__device__ int g_offA[NA_MAX];
__device__ int g_eidxC[EC_MAX];
__device__ int g_eidxW[EW_MAX];
__device__ int g_eidxR[EW_MAX];

// ---------------- fused small kernels ----------------
__global__ void zero_all(int* __restrict__ dC, int* __restrict__ dW, int* __restrict__ dA,
                         int np, int na) {
  int i = blockIdx.x * blockDim.x + threadIdx.x;
  if (i < np) { dC[i] = 0; dW[i] = 0; }
  if (i < na) dA[i] = 0;
}

__global__ void count_all(const int* __restrict__ cd, const int* __restrict__ wd,
                          const int* __restrict__ rd,
                          int* __restrict__ dC, int* __restrict__ dW, int* __restrict__ dA,
                          int ec, int ew, int er) {
  int i = blockIdx.x * blockDim.x + threadIdx.x;
  if (i < ec) atomicAdd(dC + __ldg(cd + i), 1);
  else if (i < ec + ew) atomicAdd(dW + __ldg(wd + i - ec), 1);
  else if (i < ec + ew + er) atomicAdd(dA + __ldg(rd + i - ec - ew), 1);
}

// one block per array; sequential 1024-chunk exclusive scan
__global__ void scan3_kernel(const int* c0, int* o0, int n0,
                             const int* c1, int* o1, int n1,
                             const int* c2, int* o2, int n2) {
  const int* c; int* o; int n;
  if (blockIdx.x == 0) { c = c0; o = o0; n = n0; }
  else if (blockIdx.x == 1) { c = c1; o = o1; n = n1; }
  else { c = c2; o = o2; n = n2; }
  __shared__ int wsum[32];
  __shared__ int carry;
  if (threadIdx.x == 0) carry = 0;
  __syncthreads();
  int lane = threadIdx.x & 31, wid = threadIdx.x >> 5;
  for (int base = 0; base < n; base += 1024) {
    int i = base + threadIdx.x;
    int v = (i < n) ? c[i] : 0;
    int x = v;
#pragma unroll
    for (int off = 1; off < 32; off <<= 1) {
      int y = __shfl_up_sync(0xffffffffu, x, off);
      if (lane >= off) x += y;
    }
    if (lane == 31) wsum[wid] = x;
    __syncthreads();
    if (threadIdx.x < 32) {
      int y = wsum[threadIdx.x];
#pragma unroll
      for (int off = 1; off < 32; off <<= 1) {
        int z = __shfl_up_sync(0xffffffffu, y, off);
        if (threadIdx.x >= off) y += z;
      }
      wsum[threadIdx.x] = y;
    }
    __syncthreads();
    int incl = carry + (wid > 0 ? wsum[wid - 1] : 0) + x;
    if (i < n) o[i] = incl - v;    // exclusive
    __syncthreads();
    if (threadIdx.x == 1023) carry += wsum[31];
    __syncthreads();
  }
}

__global__ void permute_all(const int* __restrict__ cs, const int* __restrict__ cd,
                            const int* __restrict__ ws, const int* __restrict__ wd,
                            const int* __restrict__ rs, const int* __restrict__ rd,
                            int* __restrict__ oC, int* __restrict__ oW, int* __restrict__ oA,
                            int* __restrict__ eC, int* __restrict__ eW, int* __restrict__ eR,
                            int ec, int ew, int er) {
  int i = blockIdx.x * blockDim.x + threadIdx.x;
  if (i < ec) {
    int pos = atomicAdd(oC + __ldg(cd + i), 1);
    eC[pos] = __ldg(cs + i);
  } else if (i < ec + ew) {
    int j = i - ec;
    int pos = atomicAdd(oW + __ldg(wd + j), 1);
    eW[pos] = __ldg(ws + j);
  } else if (i < ec + ew + er) {
    int j = i - ec - ew;
    int pos = atomicAdd(oA + __ldg(rd + j), 1);
    eR[pos] = __ldg(rs + j);
  }
}

// ---------------- gather-mean: warp per dst node, 3 segments, 4-way unroll ----------------
__global__ void gather_all(const float* __restrict__ xp, const float* __restrict__ xa,
                           const int* __restrict__ eC, const int* __restrict__ oC, const int* __restrict__ dC,
                           const int* __restrict__ eW, const int* __restrict__ oW, const int* __restrict__ dW,
                           const int* __restrict__ eR, const int* __restrict__ oA, const int* __restrict__ dA,
                           float* __restrict__ aggC, float* __restrict__ aggW, float* __restrict__ aggA,
                           int np, int na) {
  int gw = (blockIdx.x * blockDim.x + threadIdx.x) >> 5;
  int lane = threadIdx.x & 31;
  const float* x; const int* ei; const int* offe; const int* deg; float* outm; int n;
  if (gw < np)            { x = xp; ei = eC; offe = oC; deg = dC; outm = aggC; n = gw; }
  else if (gw < 2 * np)   { x = xa; ei = eW; offe = oW; deg = dW; outm = aggW; n = gw - np; }
  else if (gw < 2 * np + na) { x = xp; ei = eR; offe = oA; deg = dA; outm = aggA; n = gw - 2 * np; }
  else return;

  int d = __ldg(deg + n);
  int end = __ldg(offe + n);
  int e = end - d;
  float4 acc = make_float4(0.f, 0.f, 0.f, 0.f);
  for (; e + 3 < end; e += 4) {
    int s0 = __ldg(ei + e), s1 = __ldg(ei + e + 1), s2 = __ldg(ei + e + 2), s3 = __ldg(ei + e + 3);
    float4 v0 = __ldg((const float4*)(x + (size_t)s0 * H) + lane);
    float4 v1 = __ldg((const float4*)(x + (size_t)s1 * H) + lane);
    float4 v2 = __ldg((const float4*)(x + (size_t)s2 * H) + lane);
    float4 v3 = __ldg((const float4*)(x + (size_t)s3 * H) + lane);
    acc.x += v0.x + v1.x + v2.x + v3.x;
    acc.y += v0.y + v1.y + v2.y + v3.y;
    acc.z += v0.z + v1.z + v2.z + v3.z;
    acc.w += v0.w + v1.w + v2.w + v3.w;
  }
  for (; e < end; e++) {
    int s0 = __ldg(ei + e);
    float4 v0 = __ldg((const float4*)(x + (size_t)s0 * H) + lane);
    acc.x += v0.x; acc.y += v0.y; acc.z += v0.z; acc.w += v0.w;
  }
  float iv = 1.0f / (float)max(d, 1);
  ((float4*)(outm + (size_t)n * H))[lane] =
      make_float4(acc.x * iv, acc.y * iv, acc.z * iv, acc.w * iv);
}

// ---------------- unified sage kernel (wmma tf32, full weights in smem) ----------------
// mode 0: out = relu(normalize(mean@Wl + bl + x@Wr))                 [author]
// mode 1: out = 0.5 * normalize(...)                                 [paper sage1 -> tmp]
// mode 2: out = relu(tmp + 0.5 * normalize(...))                     [paper sage2]
typedef wmma::fragment<wmma::matrix_a, 16, 16, 8, wmma::precision::tf32, wmma::row_major> FragA;
typedef wmma::fragment<wmma::matrix_b, 16, 16, 8, wmma::precision::tf32, wmma::row_major> FragB;
typedef wmma::fragment<wmma::accumulator, 16, 16, 8, float> FragC;

#define TILE_OFF 8448        // 64 * 132
#define W_OFF 16896          // 128 * 132
#define SMEM_SAGE ((2 * TILE_OFF + 2 * W_OFF + 128) * 4)

__global__ __launch_bounds__(256) void sage_wmma(
    const float* __restrict__ x, const float* __restrict__ mean,
    const float* __restrict__ Wl, const float* __restrict__ bl, const float* __restrict__ Wr,
    const float* __restrict__ tmp, float* __restrict__ out, int N, int mode) {
  extern __shared__ float sm[];
  float* sMean = sm;                        // 64x132, later output staging
  float* sX    = sm + TILE_OFF;             // 64x132
  float* sWl   = sm + 2 * TILE_OFF;         // 128x132
  float* sWr   = sWl + W_OFF;               // 128x132
  float* sB    = sWr + W_OFF;               // 128

  int tid = threadIdx.x, wid = tid >> 5;
  int row0 = blockIdx.x * 64;

  if (tid < 128) sB[tid] = __ldg(bl + tid);
  // stage A tiles (64x128, tf32, stride 132)
  for (int idx = tid; idx < 64 * 32; idx += 256) {
    int row = idx >> 5, c4 = idx & 31;
    int r = row0 + row;
    float4 vm = make_float4(0.f, 0.f, 0.f, 0.f), vx = vm;
    if (r < N) {
      vm = __ldg((const float4*)(mean + (size_t)r * H) + c4);
      vx = __ldg((const float4*)(x + (size_t)r * H) + c4);
    }
    vm.x = wmma::__float_to_tf32(vm.x); vm.y = wmma::__float_to_tf32(vm.y);
    vm.z = wmma::__float_to_tf32(vm.z); vm.w = wmma::__float_to_tf32(vm.w);
    vx.x = wmma::__float_to_tf32(vx.x); vx.y = wmma::__float_to_tf32(vx.y);
    vx.z = wmma::__float_to_tf32(vx.z); vx.w = wmma::__float_to_tf32(vx.w);
    *(float4*)(sMean + row * 132 + c4 * 4) = vm;
    *(float4*)(sX + row * 132 + c4 * 4) = vx;
  }
  // stage full weights (128x128 each, tf32, stride 132)
  for (int idx = tid; idx < 128 * 32; idx += 256) {
    int row = idx >> 5, c4 = idx & 31;
    float4 vl = __ldg((const float4*)(Wl + (size_t)row * H) + c4);
    float4 vr = __ldg((const float4*)(Wr + (size_t)row * H) + c4);
    vl.x = wmma::__float_to_tf32(vl.x); vl.y = wmma::__float_to_tf32(vl.y);
    vl.z = wmma::__float_to_tf32(vl.z); vl.w = wmma::__float_to_tf32(vl.w);
    vr.x = wmma::__float_to_tf32(vr.x); vr.y = wmma::__float_to_tf32(vr.y);
    vr.z = wmma::__float_to_tf32(vr.z); vr.w = wmma::__float_to_tf32(vr.w);
    *(float4*)(sWl + row * 132 + c4 * 4) = vl;
    *(float4*)(sWr + row * 132 + c4 * 4) = vr;
  }
  __syncthreads();

  // warp (wid&3) -> rows mrow..mrow+15, (wid>>2) -> cols ncol..ncol+63
  int mrow = (wid & 3) * 16;
  int ncol = (wid >> 2) * 64;

  FragC acc[4];
#pragma unroll
  for (int n = 0; n < 4; n++) wmma::fill_fragment(acc[n], 0.0f);

  FragA a1, a2;
  FragB b1, b2;
#pragma unroll 4
  for (int kf = 0; kf < 16; kf++) {
    wmma::load_matrix_sync(a1, sMean + mrow * 132 + kf * 8, 132);
    wmma::load_matrix_sync(a2, sX + mrow * 132 + kf * 8, 132);
#pragma unroll
    for (int n = 0; n < 4; n++) {
      int col = ncol + n * 16;
      wmma::load_matrix_sync(b1, sWl + kf * 8 * 132 + col, 132);
      wmma::load_matrix_sync(b2, sWr + kf * 8 * 132 + col, 132);
      wmma::mma_sync(acc[n], a1, b1, acc[n]);
      wmma::mma_sync(acc[n], a2, b2, acc[n]);
    }
  }

  __syncthreads();   // everyone done reading sMean/sX
#pragma unroll
  for (int n = 0; n < 4; n++)
    wmma::store_matrix_sync(sMean + mrow * 132 + ncol + n * 16, acc[n], 132, wmma::mem_row_major);
  __syncthreads();

  // epilogue: 4 threads per row (quad via lanes 0-3 pattern), 32 cols each
  int row = tid >> 2, q = tid & 3;
  const float* o1 = sMean + row * 132 + q * 32;
  const float* bp = sB + q * 32;
  float ss = 0.f;
#pragma unroll
  for (int j = 0; j < 8; j++) {
    float4 v = *(const float4*)(o1 + j * 4);
    float t;
    t = v.x + bp[j * 4 + 0]; ss += t * t;
    t = v.y + bp[j * 4 + 1]; ss += t * t;
    t = v.z + bp[j * 4 + 2]; ss += t * t;
    t = v.w + bp[j * 4 + 3]; ss += t * t;
  }
  ss += __shfl_xor_sync(0xffffffffu, ss, 1);
  ss += __shfl_xor_sync(0xffffffffu, ss, 2);
  float wgt = (mode == 0) ? 1.0f : 0.5f;
  float rn = wgt / fmaxf(sqrtf(ss), 1e-12f);

  int r = row0 + row;
  if (r < N) {
    float* op = out + (size_t)r * H + q * 32;
    const float* tp = tmp + (size_t)r * H + q * 32;   // only read in mode 2
#pragma unroll
    for (int j = 0; j < 8; j++) {
      float4 v = *(const float4*)(o1 + j * 4);
      float4 o;
      o.x = (v.x + bp[j * 4 + 0]) * rn;
      o.y = (v.y + bp[j * 4 + 1]) * rn;
      o.z = (v.z + bp[j * 4 + 2]) * rn;
      o.w = (v.w + bp[j * 4 + 3]) * rn;
      if (mode == 2) {
        float4 t = __ldg((const float4*)(tp + j * 4));
        o.x += t.x; o.y += t.y; o.z += t.z; o.w += t.w;
      }
      if (mode != 1) {
        o.x = fmaxf(o.x, 0.f); o.y = fmaxf(o.y, 0.f);
        o.z = fmaxf(o.z, 0.f); o.w = fmaxf(o.w, 0.f);
      }
      *(float4*)(op + j * 4) = o;
    }
  }
}

// ---------------- launch ----------------
extern "C" void kernel_launch(void* const* d_in, const int* in_sizes, int n_in,
                              void* d_out, int out_size) {
  const float* x_paper = (const float*)d_in[0];
  const float* x_author = (const float*)d_in[1];
  const int* cs = (const int*)d_in[2];
  const int* cd = (const int*)d_in[3];
  const int* ws = (const int*)d_in[4];
  const int* wd = (const int*)d_in[5];
  const int* rs = (const int*)d_in[6];
  const int* rd = (const int*)d_in[7];
  const float* P[18];
  for (int i = 0; i < 18; i++) P[i] = (const float*)d_in[8 + i];

  int NPn = in_sizes[0] / H;   // 100000
  int NAn = in_sizes[1] / H;   // 50000
  int EC = in_sizes[2];
  int EW = in_sizes[4];
  int ER = in_sizes[6];

  float *aggC, *aggW, *aggA, *xp1, *xa1;
  int *degC, *degW, *degA, *offC, *offW, *offA, *eiC, *eiW, *eiR;
  cudaGetSymbolAddress((void**)&aggC, g_aggC);
  cudaGetSymbolAddress((void**)&aggW, g_aggW);
  cudaGetSymbolAddress((void**)&aggA, g_aggA);
  cudaGetSymbolAddress((void**)&xp1, g_xp);
  cudaGetSymbolAddress((void**)&xa1, g_xa);
  cudaGetSymbolAddress((void**)&degC, g_degC);
  cudaGetSymbolAddress((void**)&degW, g_degW);
  cudaGetSymbolAddress((void**)&degA, g_degA);
  cudaGetSymbolAddress((void**)&offC, g_offC);
  cudaGetSymbolAddress((void**)&offW, g_offW);
  cudaGetSymbolAddress((void**)&offA, g_offA);
  cudaGetSymbolAddress((void**)&eiC, g_eidxC);
  cudaGetSymbolAddress((void**)&eiW, g_eidxW);
  cudaGetSymbolAddress((void**)&eiR, g_eidxR);

  cudaFuncSetAttribute((const void*)sage_wmma,
                       cudaFuncAttributeMaxDynamicSharedMemorySize, SMEM_SAGE);

  int Etot = EC + EW + ER;
  int Ntot = 2 * NPn + NAn;

  // ---- CSR build: 4 launches ----
  zero_all<<<(NPn + 255) / 256, 256>>>(degC, degW, degA, NPn, NAn);
  count_all<<<(Etot + 255) / 256, 256>>>(cd, wd, rd, degC, degW, degA, EC, EW, ER);
  scan3_kernel<<<3, 1024>>>(degC, offC, NPn, degW, offW, NPn, degA, offA, NAn);
  permute_all<<<(Etot + 255) / 256, 256>>>(cs, cd, ws, wd, rs, rd,
                                           offC, offW, offA, eiC, eiW, eiR, EC, EW, ER);
  // after permute: off* hold END offsets; start = end - deg

  int gG = (Ntot * 32 + 255) / 256;
  int gridP = (NPn + 63) / 64;
  int gridA = (NAn + 63) / 64;

  float* outp = (float*)d_out;
  float* outa = (float*)d_out + (size_t)NPn * H;

  // ---- layer 1 ---- (launch index 5 = paper sage1: ncu profiles it)
  gather_all<<<gG, 256>>>(x_paper, x_author, eiC, offC, degC, eiW, offW, degW,
                          eiR, offA, degA, aggC, aggW, aggA, NPn, NAn);
  sage_wmma<<<gridP, 256, SMEM_SAGE>>>(x_paper, aggC, P[0], P[1], P[2],
                                       nullptr, aggC, NPn, 1);   // tmp <- 0.5*n1 (aliases aggC)
  sage_wmma<<<gridP, 256, SMEM_SAGE>>>(x_paper, aggW, P[3], P[4], P[5],
                                       aggC, xp1, NPn, 2);
  sage_wmma<<<gridA, 256, SMEM_SAGE>>>(x_author, aggA, P[6], P[7], P[8],
                                       nullptr, xa1, NAn, 0);

  // ---- layer 2 ----
  gather_all<<<gG, 256>>>(xp1, xa1, eiC, offC, degC, eiW, offW, degW,
                          eiR, offA, degA, aggC, aggW, aggA, NPn, NAn);
  sage_wmma<<<gridP, 256, SMEM_SAGE>>>(xp1, aggC, P[9], P[10], P[11],
                                       nullptr, aggC, NPn, 1);
  sage_wmma<<<gridP, 256, SMEM_SAGE>>>(xp1, aggW, P[12], P[13], P[14],
                                       aggC, outp, NPn, 2);
  sage_wmma<<<gridA, 256, SMEM_SAGE>>>(xa1, aggA, P[15], P[16], P[17],
                                       nullptr, outa, NAn, 0);
}

// round 8
// speedup vs baseline: 1.0088x; 1.0088x over previous
#include <cuda_runtime.h>
#include <mma.h>
#include <cstdint>

using namespace nvcuda;

#define H 128
#define NP_MAX 100000
#define NA_MAX 50000
#define EC_MAX 1000000
#define EW_MAX 320000

// ---------------- scratch (static device globals; no allocation) ----------------
__device__ float g_aggC[NP_MAX * H];   // mean(cites); later reused as paper tmp (0.5*n1)
__device__ float g_aggW[NP_MAX * H];   // mean(writes)
__device__ float g_aggA[NA_MAX * H];   // mean(rev)
__device__ float g_xp[NP_MAX * H];
__device__ float g_xa[NA_MAX * H];
__device__ int g_degC[NP_MAX];
__device__ int g_degW[NP_MAX];
__device__ int g_degA[NA_MAX];
__device__ int g_offC[NP_MAX];         // after permute: END offsets
__device__ int g_offW[NP_MAX];
__device__ int g_offA[NA_MAX];
__device__ int g_eidxC[EC_MAX];
__device__ int g_eidxW[EW_MAX];
__device__ int g_eidxR[EW_MAX];

// ---------------- fused small kernels ----------------
__global__ void zero_all(int* __restrict__ dC, int* __restrict__ dW, int* __restrict__ dA,
                         int np, int na) {
  int i = blockIdx.x * blockDim.x + threadIdx.x;
  if (i < np) { dC[i] = 0; dW[i] = 0; }
  if (i < na) dA[i] = 0;
}

__global__ void count_all(const int* __restrict__ cd, const int* __restrict__ wd,
                          const int* __restrict__ rd,
                          int* __restrict__ dC, int* __restrict__ dW, int* __restrict__ dA,
                          int ec, int ew, int er) {
  int i = blockIdx.x * blockDim.x + threadIdx.x;
  if (i < ec) atomicAdd(dC + __ldg(cd + i), 1);
  else if (i < ec + ew) atomicAdd(dW + __ldg(wd + i - ec), 1);
  else if (i < ec + ew + er) atomicAdd(dA + __ldg(rd + i - ec - ew), 1);
}

// one block per array; sequential 1024-chunk exclusive scan
__global__ void scan3_kernel(const int* c0, int* o0, int n0,
                             const int* c1, int* o1, int n1,
                             const int* c2, int* o2, int n2) {
  const int* c; int* o; int n;
  if (blockIdx.x == 0) { c = c0; o = o0; n = n0; }
  else if (blockIdx.x == 1) { c = c1; o = o1; n = n1; }
  else { c = c2; o = o2; n = n2; }
  __shared__ int wsum[32];
  __shared__ int carry;
  if (threadIdx.x == 0) carry = 0;
  __syncthreads();
  int lane = threadIdx.x & 31, wid = threadIdx.x >> 5;
  for (int base = 0; base < n; base += 1024) {
    int i = base + threadIdx.x;
    int v = (i < n) ? c[i] : 0;
    int x = v;
#pragma unroll
    for (int off = 1; off < 32; off <<= 1) {
      int y = __shfl_up_sync(0xffffffffu, x, off);
      if (lane >= off) x += y;
    }
    if (lane == 31) wsum[wid] = x;
    __syncthreads();
    if (threadIdx.x < 32) {
      int y = wsum[threadIdx.x];
#pragma unroll
      for (int off = 1; off < 32; off <<= 1) {
        int z = __shfl_up_sync(0xffffffffu, y, off);
        if (threadIdx.x >= off) y += z;
      }
      wsum[threadIdx.x] = y;
    }
    __syncthreads();
    int incl = carry + (wid > 0 ? wsum[wid - 1] : 0) + x;
    if (i < n) o[i] = incl - v;    // exclusive
    __syncthreads();
    if (threadIdx.x == 1023) carry += wsum[31];
    __syncthreads();
  }
}

__global__ void permute_all(const int* __restrict__ cs, const int* __restrict__ cd,
                            const int* __restrict__ ws, const int* __restrict__ wd,
                            const int* __restrict__ rs, const int* __restrict__ rd,
                            int* __restrict__ oC, int* __restrict__ oW, int* __restrict__ oA,
                            int* __restrict__ eC, int* __restrict__ eW, int* __restrict__ eR,
                            int ec, int ew, int er) {
  int i = blockIdx.x * blockDim.x + threadIdx.x;
  if (i < ec) {
    int pos = atomicAdd(oC + __ldg(cd + i), 1);
    eC[pos] = __ldg(cs + i);
  } else if (i < ec + ew) {
    int j = i - ec;
    int pos = atomicAdd(oW + __ldg(wd + j), 1);
    eW[pos] = __ldg(ws + j);
  } else if (i < ec + ew + er) {
    int j = i - ec - ew;
    int pos = atomicAdd(oA + __ldg(rd + j), 1);
    eR[pos] = __ldg(rs + j);
  }
}

// ---------------- gather-mean: warp per dst node, 3 segments, 4-way unroll ----------------
__global__ void gather_all(const float* __restrict__ xp, const float* __restrict__ xa,
                           const int* __restrict__ eC, const int* __restrict__ oC, const int* __restrict__ dC,
                           const int* __restrict__ eW, const int* __restrict__ oW, const int* __restrict__ dW,
                           const int* __restrict__ eR, const int* __restrict__ oA, const int* __restrict__ dA,
                           float* __restrict__ aggC, float* __restrict__ aggW, float* __restrict__ aggA,
                           int np, int na) {
  int gw = (blockIdx.x * blockDim.x + threadIdx.x) >> 5;
  int lane = threadIdx.x & 31;
  const float* x; const int* ei; const int* offe; const int* deg; float* outm; int n;
  if (gw < np)            { x = xp; ei = eC; offe = oC; deg = dC; outm = aggC; n = gw; }
  else if (gw < 2 * np)   { x = xa; ei = eW; offe = oW; deg = dW; outm = aggW; n = gw - np; }
  else if (gw < 2 * np + na) { x = xp; ei = eR; offe = oA; deg = dA; outm = aggA; n = gw - 2 * np; }
  else return;

  int d = __ldg(deg + n);
  int end = __ldg(offe + n);
  int e = end - d;
  float4 acc = make_float4(0.f, 0.f, 0.f, 0.f);
  for (; e + 3 < end; e += 4) {
    int s0 = __ldg(ei + e), s1 = __ldg(ei + e + 1), s2 = __ldg(ei + e + 2), s3 = __ldg(ei + e + 3);
    float4 v0 = __ldg((const float4*)(x + (size_t)s0 * H) + lane);
    float4 v1 = __ldg((const float4*)(x + (size_t)s1 * H) + lane);
    float4 v2 = __ldg((const float4*)(x + (size_t)s2 * H) + lane);
    float4 v3 = __ldg((const float4*)(x + (size_t)s3 * H) + lane);
    acc.x += v0.x + v1.x + v2.x + v3.x;
    acc.y += v0.y + v1.y + v2.y + v3.y;
    acc.z += v0.z + v1.z + v2.z + v3.z;
    acc.w += v0.w + v1.w + v2.w + v3.w;
  }
  for (; e < end; e++) {
    int s0 = __ldg(ei + e);
    float4 v0 = __ldg((const float4*)(x + (size_t)s0 * H) + lane);
    acc.x += v0.x; acc.y += v0.y; acc.z += v0.z; acc.w += v0.w;
  }
  float iv = 1.0f / (float)max(d, 1);
  ((float4*)(outm + (size_t)n * H))[lane] =
      make_float4(acc.x * iv, acc.y * iv, acc.z * iv, acc.w * iv);
}

// ---------------- unified sage kernel (wmma tf32, full weights in smem) ----------------
// mode 0: out = relu(normalize(mean@Wl + bl + x@Wr))                 [author]
// mode 1: out = 0.5 * normalize(...)                                 [paper sage1 -> tmp]
// mode 2: out = relu(tmp + 0.5 * normalize(...))                     [paper sage2]
typedef wmma::fragment<wmma::matrix_a, 16, 16, 8, wmma::precision::tf32, wmma::row_major> FragA;
typedef wmma::fragment<wmma::matrix_b, 16, 16, 8, wmma::precision::tf32, wmma::row_major> FragB;
typedef wmma::fragment<wmma::accumulator, 16, 16, 8, float> FragC;

#define TILE_OFF 8448        // 64 * 132
#define W_OFF 16896          // 128 * 132
#define SMEM_SAGE ((2 * TILE_OFF + 2 * W_OFF + 128) * 4)

__global__ __launch_bounds__(256) void sage_wmma(
    const float* __restrict__ x, const float* __restrict__ mean,
    const float* __restrict__ Wl, const float* __restrict__ bl, const float* __restrict__ Wr,
    const float* __restrict__ tmp, float* __restrict__ out, int N, int mode) {
  extern __shared__ float sm[];
  float* sMean = sm;                        // 64x132, later output staging
  float* sX    = sm + TILE_OFF;             // 64x132
  float* sWl   = sm + 2 * TILE_OFF;         // 128x132
  float* sWr   = sWl + W_OFF;               // 128x132
  float* sB    = sWr + W_OFF;               // 128

  int tid = threadIdx.x, wid = tid >> 5;
  int row0 = blockIdx.x * 64;

  if (tid < 128) sB[tid] = __ldg(bl + tid);
  // stage A tiles (64x128, tf32, stride 132)
  for (int idx = tid; idx < 64 * 32; idx += 256) {
    int row = idx >> 5, c4 = idx & 31;
    int r = row0 + row;
    float4 vm = make_float4(0.f, 0.f, 0.f, 0.f), vx = vm;
    if (r < N) {
      vm = __ldg((const float4*)(mean + (size_t)r * H) + c4);
      vx = __ldg((const float4*)(x + (size_t)r * H) + c4);
    }
    vm.x = wmma::__float_to_tf32(vm.x); vm.y = wmma::__float_to_tf32(vm.y);
    vm.z = wmma::__float_to_tf32(vm.z); vm.w = wmma::__float_to_tf32(vm.w);
    vx.x = wmma::__float_to_tf32(vx.x); vx.y = wmma::__float_to_tf32(vx.y);
    vx.z = wmma::__float_to_tf32(vx.z); vx.w = wmma::__float_to_tf32(vx.w);
    *(float4*)(sMean + row * 132 + c4 * 4) = vm;
    *(float4*)(sX + row * 132 + c4 * 4) = vx;
  }
  // stage full weights (128x128 each, tf32, stride 132)
  for (int idx = tid; idx < 128 * 32; idx += 256) {
    int row = idx >> 5, c4 = idx & 31;
    float4 vl = __ldg((const float4*)(Wl + (size_t)row * H) + c4);
    float4 vr = __ldg((const float4*)(Wr + (size_t)row * H) + c4);
    vl.x = wmma::__float_to_tf32(vl.x); vl.y = wmma::__float_to_tf32(vl.y);
    vl.z = wmma::__float_to_tf32(vl.z); vl.w = wmma::__float_to_tf32(vl.w);
    vr.x = wmma::__float_to_tf32(vr.x); vr.y = wmma::__float_to_tf32(vr.y);
    vr.z = wmma::__float_to_tf32(vr.z); vr.w = wmma::__float_to_tf32(vr.w);
    *(float4*)(sWl + row * 132 + c4 * 4) = vl;
    *(float4*)(sWr + row * 132 + c4 * 4) = vr;
  }
  __syncthreads();

  // warp (wid&3) -> rows mrow..mrow+15, (wid>>2) -> cols ncol..ncol+63
  int mrow = (wid & 3) * 16;
  int ncol = (wid >> 2) * 64;

  FragC acc[4];
#pragma unroll
  for (int n = 0; n < 4; n++) wmma::fill_fragment(acc[n], 0.0f);

  FragA a1, a2;
  FragB b1, b2;
#pragma unroll 4
  for (int kf = 0; kf < 16; kf++) {
    wmma::load_matrix_sync(a1, sMean + mrow * 132 + kf * 8, 132);
    wmma::load_matrix_sync(a2, sX + mrow * 132 + kf * 8, 132);
#pragma unroll
    for (int n = 0; n < 4; n++) {
      int col = ncol + n * 16;
      wmma::load_matrix_sync(b1, sWl + kf * 8 * 132 + col, 132);
      wmma::load_matrix_sync(b2, sWr + kf * 8 * 132 + col, 132);
      wmma::mma_sync(acc[n], a1, b1, acc[n]);
      wmma::mma_sync(acc[n], a2, b2, acc[n]);
    }
  }

  __syncthreads();   // everyone done reading sMean/sX
#pragma unroll
  for (int n = 0; n < 4; n++)
    wmma::store_matrix_sync(sMean + mrow * 132 + ncol + n * 16, acc[n], 132, wmma::mem_row_major);
  __syncthreads();

  // epilogue: 4 threads per row (quad via lanes 0-3 pattern), 32 cols each
  int row = tid >> 2, q = tid & 3;
  const float* o1 = sMean + row * 132 + q * 32;
  const float* bp = sB + q * 32;
  float ss = 0.f;
#pragma unroll
  for (int j = 0; j < 8; j++) {
    float4 v = *(const float4*)(o1 + j * 4);
    float t;
    t = v.x + bp[j * 4 + 0]; ss += t * t;
    t = v.y + bp[j * 4 + 1]; ss += t * t;
    t = v.z + bp[j * 4 + 2]; ss += t * t;
    t = v.w + bp[j * 4 + 3]; ss += t * t;
  }
  ss += __shfl_xor_sync(0xffffffffu, ss, 1);
  ss += __shfl_xor_sync(0xffffffffu, ss, 2);
  float wgt = (mode == 0) ? 1.0f : 0.5f;
  float rn = wgt / fmaxf(sqrtf(ss), 1e-12f);

  int r = row0 + row;
  if (r < N) {
    float* op = out + (size_t)r * H + q * 32;
    const float* tp = tmp + (size_t)r * H + q * 32;   // only read in mode 2
#pragma unroll
    for (int j = 0; j < 8; j++) {
      float4 v = *(const float4*)(o1 + j * 4);
      float4 o;
      o.x = (v.x + bp[j * 4 + 0]) * rn;
      o.y = (v.y + bp[j * 4 + 1]) * rn;
      o.z = (v.z + bp[j * 4 + 2]) * rn;
      o.w = (v.w + bp[j * 4 + 3]) * rn;
      if (mode == 2) {
        float4 t = __ldg((const float4*)(tp + j * 4));
        o.x += t.x; o.y += t.y; o.z += t.z; o.w += t.w;
      }
      if (mode != 1) {
        o.x = fmaxf(o.x, 0.f); o.y = fmaxf(o.y, 0.f);
        o.z = fmaxf(o.z, 0.f); o.w = fmaxf(o.w, 0.f);
      }
      *(float4*)(op + j * 4) = o;
    }
  }
}

// ---------------- launch ----------------
extern "C" void kernel_launch(void* const* d_in, const int* in_sizes, int n_in,
                              void* d_out, int out_size) {
  const float* x_paper = (const float*)d_in[0];
  const float* x_author = (const float*)d_in[1];
  const int* cs = (const int*)d_in[2];
  const int* cd = (const int*)d_in[3];
  const int* ws = (const int*)d_in[4];
  const int* wd = (const int*)d_in[5];
  const int* rs = (const int*)d_in[6];
  const int* rd = (const int*)d_in[7];
  const float* P[18];
  for (int i = 0; i < 18; i++) P[i] = (const float*)d_in[8 + i];

  int NPn = in_sizes[0] / H;   // 100000
  int NAn = in_sizes[1] / H;   // 50000
  int EC = in_sizes[2];
  int EW = in_sizes[4];
  int ER = in_sizes[6];

  float *aggC, *aggW, *aggA, *xp1, *xa1;
  int *degC, *degW, *degA, *offC, *offW, *offA, *eiC, *eiW, *eiR;
  cudaGetSymbolAddress((void**)&aggC, g_aggC);
  cudaGetSymbolAddress((void**)&aggW, g_aggW);
  cudaGetSymbolAddress((void**)&aggA, g_aggA);
  cudaGetSymbolAddress((void**)&xp1, g_xp);
  cudaGetSymbolAddress((void**)&xa1, g_xa);
  cudaGetSymbolAddress((void**)&degC, g_degC);
  cudaGetSymbolAddress((void**)&degW, g_degW);
  cudaGetSymbolAddress((void**)&degA, g_degA);
  cudaGetSymbolAddress((void**)&offC, g_offC);
  cudaGetSymbolAddress((void**)&offW, g_offW);
  cudaGetSymbolAddress((void**)&offA, g_offA);
  cudaGetSymbolAddress((void**)&eiC, g_eidxC);
  cudaGetSymbolAddress((void**)&eiW, g_eidxW);
  cudaGetSymbolAddress((void**)&eiR, g_eidxR);

  cudaFuncSetAttribute((const void*)sage_wmma,
                       cudaFuncAttributeMaxDynamicSharedMemorySize, SMEM_SAGE);

  int Etot = EC + EW + ER;
  int Ntot = 2 * NPn + NAn;

  // ---- CSR build: 4 launches ----
  zero_all<<<(NPn + 255) / 256, 256>>>(degC, degW, degA, NPn, NAn);
  count_all<<<(Etot + 255) / 256, 256>>>(cd, wd, rd, degC, degW, degA, EC, EW, ER);
  scan3_kernel<<<3, 1024>>>(degC, offC, NPn, degW, offW, NPn, degA, offA, NAn);
  permute_all<<<(Etot + 255) / 256, 256>>>(cs, cd, ws, wd, rs, rd,
                                           offC, offW, offA, eiC, eiW, eiR, EC, EW, ER);
  // after permute: off* hold END offsets; start = end - deg

  int gG = (Ntot * 32 + 255) / 256;
  int gridP = (NPn + 63) / 64;
  int gridA = (NAn + 63) / 64;

  float* outp = (float*)d_out;
  float* outa = (float*)d_out + (size_t)NPn * H;

  // ---- layer 1 ---- (launch index 5 = paper sage1: ncu profiles it)
  gather_all<<<gG, 256>>>(x_paper, x_author, eiC, offC, degC, eiW, offW, degW,
                          eiR, offA, degA, aggC, aggW, aggA, NPn, NAn);
  sage_wmma<<<gridP, 256, SMEM_SAGE>>>(x_paper, aggC, P[0], P[1], P[2],
                                       nullptr, aggC, NPn, 1);   // tmp <- 0.5*n1 (aliases aggC)
  sage_wmma<<<gridP, 256, SMEM_SAGE>>>(x_paper, aggW, P[3], P[4], P[5],
                                       aggC, xp1, NPn, 2);
  sage_wmma<<<gridA, 256, SMEM_SAGE>>>(x_author, aggA, P[6], P[7], P[8],
                                       nullptr, xa1, NAn, 0);

  // ---- layer 2 ----
  gather_all<<<gG, 256>>>(xp1, xa1, eiC, offC, degC, eiW, offW, degW,
                          eiR, offA, degA, aggC, aggW, aggA, NPn, NAn);
  sage_wmma<<<gridP, 256, SMEM_SAGE>>>(xp1, aggC, P[9], P[10], P[11],
                                       nullptr, aggC, NPn, 1);
  sage_wmma<<<gridP, 256, SMEM_SAGE>>>(xp1, aggW, P[12], P[13], P[14],
                                       aggC, outp, NPn, 2);
  sage_wmma<<<gridA, 256, SMEM_SAGE>>>(xa1, aggA, P[15], P[16], P[17],
                                       nullptr, outa, NAn, 0);
}